// round 6
// baseline (speedup 1.0000x reference)
#include <cuda_runtime.h>
#include <cstdint>

static constexpr int BATCH = 4;
static constexpr int SEQ   = 2048;
static constexpr int DIM   = 1024;

// Scratch (device globals: allocation-guard safe)
__device__ float g_x [BATCH * SEQ * DIM];   // tf32-rounded x
__device__ float g_wq[DIM * DIM];           // tf32-rounded weights
__device__ float g_wk[DIM * DIM];
__device__ float g_wv[DIM * DIM];
__device__ float g_q [BATCH * SEQ * DIM];   // tf32-rounded Q
__device__ float g_k [BATCH * SEQ * DIM];   // tf32-rounded K
__device__ float g_v [BATCH * SEQ * DIM];   // tf32-rounded V
__device__ float g_p [BATCH * SEQ * SEQ];   // tf32-rounded attention weights

// ---------------------------------------------------------------------------
__device__ __forceinline__ float round_tf32(float x) {
    uint32_t u;
    asm("cvt.rna.tf32.f32 %0, %1;" : "=r"(u) : "f"(x));
    return __uint_as_float(u);
}

__device__ __forceinline__ void mma_tf32(float (&c)[4],
                                         uint32_t a0, uint32_t a1,
                                         uint32_t a2, uint32_t a3,
                                         uint32_t b0, uint32_t b1) {
    asm volatile(
        "mma.sync.aligned.m16n8k8.row.col.f32.tf32.tf32.f32 "
        "{%0,%1,%2,%3}, {%4,%5,%6,%7}, {%8,%9}, {%0,%1,%2,%3};\n"
        : "+f"(c[0]), "+f"(c[1]), "+f"(c[2]), "+f"(c[3])
        : "r"(a0), "r"(a1), "r"(a2), "r"(a3), "r"(b0), "r"(b1));
}

#define CPA16(dst, src) \
    asm volatile("cp.async.cg.shared.global [%0], [%1], 16;\n" :: "r"(dst), "l"(src))

// ---------------------------------------------------------------------------
// Elementwise tf32 rounding pass (float4)
// ---------------------------------------------------------------------------
__global__ __launch_bounds__(256)
void round_kernel(const float* __restrict__ in, float* __restrict__ out, int n4)
{
    int i = blockIdx.x * 256 + threadIdx.x;
    if (i < n4) {
        float4 v = ((const float4*)in)[i];
        v.x = round_tf32(v.x);
        v.y = round_tf32(v.y);
        v.z = round_tf32(v.z);
        v.w = round_tf32(v.w);
        ((float4*)out)[i] = v;
    }
}

// ---------------------------------------------------------------------------
// TF32 tensor-core GEMM, cvt-free inner loop (operands pre-rounded to tf32).
//   C = alpha * A @ op(B) (+ bias)  [optionally tf32-rounded on store]
//   A: [M,K] row-major.
//   BT=true : B stored [N,K]  (A @ B^T)
//   BT=false: B stored [K,N]
// 128x128 block tile, BK=32, 256 threads (8 warps, 64x32 warp tiles),
// cp.async double-buffered SMEM, mma.sync.m16n8k8.tf32, 2 CTAs/SM.
// ---------------------------------------------------------------------------
template <bool BT, bool ROUND_OUT>
__global__ __launch_bounds__(256, 2)
void gemm_tc(const float* __restrict__ A, const float* __restrict__ B,
             const float* __restrict__ bias, float* __restrict__ C,
             int M, int N, int K, float alpha, long sA, long sB, long sC)
{
    constexpr int BM = 128, BN = 128, BK = 32;
    constexpr int APITCH = 36;                  // As row pitch (floats)
    constexpr int BPITCH = BT ? 36 : 132;       // Bs row pitch
    constexpr int BROWS  = BT ? 128 : 32;
    constexpr int BS_OFF = 2 * BM * APITCH;     // float offset of Bs

    extern __shared__ float smem[];
    float* As = smem;
    float* Bs = smem + BS_OFF;
    uint32_t sbase;
    asm("{ .reg .u64 t; cvta.to.shared.u64 t, %1; cvt.u32.u64 %0, t; }"
        : "=r"(sbase) : "l"(smem));

    const float* Ab = A + (long)blockIdx.z * sA;
    const float* Bb = B + (long)blockIdx.z * sB;
    float*       Cb = C + (long)blockIdx.z * sC;

    const int n0   = blockIdx.x * BN;
    const int m0   = blockIdx.y * BM;
    const int tid  = threadIdx.x;
    const int warp = tid >> 5;
    const int lane = tid & 31;
    const int g    = lane >> 2;
    const int tg   = lane & 3;
    const int wm   = (warp & 1) * 64;
    const int wn   = (warp >> 1) * 32;

    const int arow = tid >> 3;            // 0..31
    const int acol = (tid & 7) * 4;       // 0..28
    const int brow = tid >> 5;            // 0..7
    const int bcol = (tid & 31) * 4;      // 0..124

    float acc[4][4][4];
    #pragma unroll
    for (int i = 0; i < 4; ++i)
        #pragma unroll
        for (int j = 0; j < 4; ++j)
            #pragma unroll
            for (int r = 0; r < 4; ++r) acc[i][j][r] = 0.0f;

    auto load_tile = [&](int kt, int buf) {
        const int k0 = kt * BK;
        #pragma unroll
        for (int i = 0; i < 4; ++i) {
            int r = arow + i * 32;
            uint32_t dst = sbase + (uint32_t)(((buf * BM + r) * APITCH + acol) * 4);
            CPA16(dst, Ab + (long)(m0 + r) * K + k0 + acol);
        }
        if (BT) {
            #pragma unroll
            for (int i = 0; i < 4; ++i) {
                int r = arow + i * 32;
                uint32_t dst = sbase + (uint32_t)((BS_OFF + (buf * BROWS + r) * BPITCH + acol) * 4);
                CPA16(dst, Bb + (long)(n0 + r) * K + k0 + acol);
            }
        } else {
            #pragma unroll
            for (int i = 0; i < 4; ++i) {
                int r = brow + i * 8;
                uint32_t dst = sbase + (uint32_t)((BS_OFF + (buf * BROWS + r) * BPITCH + bcol) * 4);
                CPA16(dst, Bb + (long)(k0 + r) * N + n0 + bcol);
            }
        }
        asm volatile("cp.async.commit_group;\n");
    };

    const int ntiles = K / BK;
    load_tile(0, 0);

    for (int kt = 0; kt < ntiles; ++kt) {
        const int buf = kt & 1;
        if (kt + 1 < ntiles) {
            load_tile(kt + 1, buf ^ 1);
            asm volatile("cp.async.wait_group 1;\n");
        } else {
            asm volatile("cp.async.wait_group 0;\n");
        }
        __syncthreads();

        #pragma unroll
        for (int kk = 0; kk < 4; ++kk) {
            const int k = kk * 8;
            uint32_t af[4][4];
            #pragma unroll
            for (int mi = 0; mi < 4; ++mi) {
                const float* ap = &As[(buf * BM + wm + mi * 16 + g) * APITCH + k];
                af[mi][0] = __float_as_uint(ap[tg]);
                af[mi][1] = __float_as_uint(ap[8 * APITCH + tg]);
                af[mi][2] = __float_as_uint(ap[tg + 4]);
                af[mi][3] = __float_as_uint(ap[8 * APITCH + tg + 4]);
            }
            uint32_t bf[4][2];
            #pragma unroll
            for (int ni = 0; ni < 4; ++ni) {
                if (BT) {
                    const float* bp = &Bs[(buf * BROWS + wn + ni * 8 + g) * BPITCH + k];
                    bf[ni][0] = __float_as_uint(bp[tg]);
                    bf[ni][1] = __float_as_uint(bp[tg + 4]);
                } else {
                    const float* bp = &Bs[(buf * BROWS + k + tg) * BPITCH + wn + ni * 8 + g];
                    bf[ni][0] = __float_as_uint(bp[0]);
                    bf[ni][1] = __float_as_uint(bp[4 * BPITCH]);
                }
            }
            #pragma unroll
            for (int mi = 0; mi < 4; ++mi)
                #pragma unroll
                for (int ni = 0; ni < 4; ++ni)
                    mma_tf32(acc[mi][ni], af[mi][0], af[mi][1], af[mi][2],
                             af[mi][3], bf[ni][0], bf[ni][1]);
        }
        __syncthreads();
    }

    // Epilogue
    #pragma unroll
    for (int mi = 0; mi < 4; ++mi) {
        const int row = m0 + wm + mi * 16 + g;
        #pragma unroll
        for (int ni = 0; ni < 4; ++ni) {
            const int col = n0 + wn + ni * 8 + tg * 2;
            float2 v0 = make_float2(acc[mi][ni][0] * alpha, acc[mi][ni][1] * alpha);
            float2 v1 = make_float2(acc[mi][ni][2] * alpha, acc[mi][ni][3] * alpha);
            if (bias) {
                float2 b = *(const float2*)&bias[col];
                v0.x += b.x; v0.y += b.y; v1.x += b.x; v1.y += b.y;
            }
            if (ROUND_OUT) {
                v0.x = round_tf32(v0.x); v0.y = round_tf32(v0.y);
                v1.x = round_tf32(v1.x); v1.y = round_tf32(v1.y);
            }
            *(float2*)&Cb[(long)row * N + col]       = v0;
            *(float2*)&Cb[(long)(row + 8) * N + col] = v1;
        }
    }
}

// ---------------------------------------------------------------------------
// In-place row softmax + tf32-rounded secondary output for the AV GEMM.
// ---------------------------------------------------------------------------
__global__ __launch_bounds__(256)
void softmax_kernel(float* __restrict__ data, float* __restrict__ rounded)
{
    constexpr int NC = SEQ;
    constexpr int PT = NC / 256;

    const long roff = (long)blockIdx.x * NC;
    float* row = data + roff;
    float* rr  = rounded + roff;
    __shared__ float red[8];

    const int tid  = threadIdx.x;
    const int lane = tid & 31;
    const int warp = tid >> 5;

    float v[PT];
    #pragma unroll
    for (int i = 0; i < PT; ++i) v[i] = row[tid + i * 256];

    float lmax = v[0];
    #pragma unroll
    for (int i = 1; i < PT; ++i) lmax = fmaxf(lmax, v[i]);
    #pragma unroll
    for (int o = 16; o > 0; o >>= 1)
        lmax = fmaxf(lmax, __shfl_xor_sync(0xFFFFFFFFu, lmax, o));
    if (lane == 0) red[warp] = lmax;
    __syncthreads();
    float rmax = red[0];
    #pragma unroll
    for (int w = 1; w < 8; ++w) rmax = fmaxf(rmax, red[w]);
    __syncthreads();

    float lsum = 0.0f;
    #pragma unroll
    for (int i = 0; i < PT; ++i) {
        v[i] = __expf(v[i] - rmax);
        lsum += v[i];
    }
    #pragma unroll
    for (int o = 16; o > 0; o >>= 1)
        lsum += __shfl_xor_sync(0xFFFFFFFFu, lsum, o);
    if (lane == 0) red[warp] = lsum;
    __syncthreads();
    float rsum = 0.0f;
    #pragma unroll
    for (int w = 0; w < 8; ++w) rsum += red[w];

    const float inv = 1.0f / rsum;
    #pragma unroll
    for (int i = 0; i < PT; ++i) {
        const float o = v[i] * inv;
        row[tid + i * 256] = o;
        rr [tid + i * 256] = round_tf32(o);
    }
}

// ---------------------------------------------------------------------------
// Launch: round(x,W) -> QKV proj -> scores -> softmax -> AV
// Output layout: [weighted_sum B*S*D | attention_weights B*S*S]
// ---------------------------------------------------------------------------
extern "C" void kernel_launch(void* const* d_in, const int* in_sizes, int n_in,
                              void* d_out, int out_size)
{
    const float* x  = (const float*)d_in[0];
    const float* Wq = (const float*)d_in[1];
    const float* bq = (const float*)d_in[2];
    const float* Wk = (const float*)d_in[3];
    const float* bk = (const float*)d_in[4];
    const float* Wv = (const float*)d_in[5];
    const float* bv = (const float*)d_in[6];

    float* out_ws = (float*)d_out;
    float* out_aw = (float*)d_out + (long)BATCH * SEQ * DIM;

    float *xr, *wq, *wk, *wv, *q, *k, *v, *p;
    cudaGetSymbolAddress((void**)&xr, g_x);
    cudaGetSymbolAddress((void**)&wq, g_wq);
    cudaGetSymbolAddress((void**)&wk, g_wk);
    cudaGetSymbolAddress((void**)&wv, g_wv);
    cudaGetSymbolAddress((void**)&q,  g_q);
    cudaGetSymbolAddress((void**)&k,  g_k);
    cudaGetSymbolAddress((void**)&v,  g_v);
    cudaGetSymbolAddress((void**)&p,  g_p);

    const int smem_bt  = 73728;
    const int smem_nbt = 70656;
    cudaFuncSetAttribute(gemm_tc<true,  true >, cudaFuncAttributeMaxDynamicSharedMemorySize, smem_bt);
    cudaFuncSetAttribute(gemm_tc<true,  false>, cudaFuncAttributeMaxDynamicSharedMemorySize, smem_bt);
    cudaFuncSetAttribute(gemm_tc<false, false>, cudaFuncAttributeMaxDynamicSharedMemorySize, smem_nbt);

    const dim3 blk(256);

    // 0) pre-round inputs to tf32 grid
    {
        const int nx = BATCH * SEQ * DIM / 4;
        const int nw = DIM * DIM / 4;
        round_kernel<<<(nx + 255) / 256, blk>>>(x,  xr, nx);
        round_kernel<<<(nw + 255) / 256, blk>>>(Wq, wq, nw);
        round_kernel<<<(nw + 255) / 256, blk>>>(Wk, wk, nw);
        round_kernel<<<(nw + 255) / 256, blk>>>(Wv, wv, nw);
    }

    // 1) QKV projections: [8192,1024] = xr @ W^T + b, tf32-rounded outputs
    {
        dim3 grid(DIM / 128, (BATCH * SEQ) / 128, 1);
        gemm_tc<true, true><<<grid, blk, smem_bt>>>(xr, wq, bq, q,
                                                    BATCH * SEQ, DIM, DIM, 1.0f, 0, 0, 0);
        gemm_tc<true, true><<<grid, blk, smem_bt>>>(xr, wk, bk, k,
                                                    BATCH * SEQ, DIM, DIM, 1.0f, 0, 0, 0);
        gemm_tc<true, true><<<grid, blk, smem_bt>>>(xr, wv, bv, v,
                                                    BATCH * SEQ, DIM, DIM, 1.0f, 0, 0, 0);
    }

    // 2) scores = (Q @ K^T) / 32, batched, exact fp32 store
    {
        dim3 grid(SEQ / 128, SEQ / 128, BATCH);
        gemm_tc<true, false><<<grid, blk, smem_bt>>>(q, k, nullptr, out_aw,
                                                     SEQ, SEQ, DIM, 0.03125f,
                                                     (long)SEQ * DIM, (long)SEQ * DIM,
                                                     (long)SEQ * SEQ);
    }

    // 3) softmax: exact -> out_aw, tf32-rounded -> p
    softmax_kernel<<<BATCH * SEQ, blk>>>(out_aw, p);

    // 4) weighted_sum = P @ V   (B stored [K=S, N=D])
    {
        dim3 grid(DIM / 128, SEQ / 128, BATCH);
        gemm_tc<false, false><<<grid, blk, smem_nbt>>>(p, v, nullptr, out_ws,
                                                       SEQ, DIM, SEQ, 1.0f,
                                                       (long)SEQ * SEQ, (long)SEQ * DIM,
                                                       (long)SEQ * DIM);
    }
}